// round 14
// baseline (speedup 1.0000x reference)
#include <cuda_runtime.h>
#include <cuda_bf16.h>
#include <cuda_fp16.h>
#include <cstdint>

#define Nn 50000
#define Ee 640000
#define Rr 8
typedef __nv_bfloat16 bf16;

// ---------------- scratch ----------------
__device__ __half g_hall[(size_t)Rr * Nn * 128];   // fp16 messages
__device__ float  g_b1[(size_t)Nn * 128];
__device__ bf16   g_Wchi[9 * 128 * 128], g_Wclo[9 * 128 * 128];   // 8 rels + w1
__device__ bf16   g_m1hi[128 * 128], g_m1lo[128 * 128];
__device__ bf16   g_m2hi[128 * 128], g_m2lo[128 * 128];

// ---------------- asm helpers ----------------
__device__ __forceinline__ uint32_t s2u(const void* p) {
    return (uint32_t)__cvta_generic_to_shared(p);
}
__device__ __forceinline__ void cp16z(uint32_t d, const void* s, int sz) {
    asm volatile("cp.async.cg.shared.global [%0],[%1],16,%2;\n" :: "r"(d), "l"(s), "r"(sz));
}
__device__ __forceinline__ void cp_commit() { asm volatile("cp.async.commit_group;\n"); }
template<int N> __device__ __forceinline__ void cp_wait() {
    asm volatile("cp.async.wait_group %0;\n" :: "n"(N));
}
__device__ __forceinline__ void ldsm4(uint32_t a, uint32_t& r0, uint32_t& r1,
                                      uint32_t& r2, uint32_t& r3) {
    asm volatile("ldmatrix.sync.aligned.m8n8.x4.shared.b16 {%0,%1,%2,%3}, [%4];"
                 : "=r"(r0), "=r"(r1), "=r"(r2), "=r"(r3) : "r"(a));
}
__device__ __forceinline__ void ldsm4t(uint32_t a, uint32_t& r0, uint32_t& r1,
                                       uint32_t& r2, uint32_t& r3) {
    asm volatile("ldmatrix.sync.aligned.m8n8.x4.trans.shared.b16 {%0,%1,%2,%3}, [%4];"
                 : "=r"(r0), "=r"(r1), "=r"(r2), "=r"(r3) : "r"(a));
}
__device__ __forceinline__ void mma16816(float& d0, float& d1, float& d2, float& d3,
                                         uint32_t a0, uint32_t a1, uint32_t a2, uint32_t a3,
                                         uint32_t b0, uint32_t b1) {
    asm volatile(
        "mma.sync.aligned.m16n8k16.row.col.f32.bf16.bf16.f32 "
        "{%0,%1,%2,%3}, {%4,%5,%6,%7}, {%8,%9}, {%0,%1,%2,%3};"
        : "+f"(d0), "+f"(d1), "+f"(d2), "+f"(d3)
        : "r"(a0), "r"(a1), "r"(a2), "r"(a3), "r"(b0), "r"(b1));
}

#define A_STRIDE 80
#define B_STRIDE 272
#define B_CHUNK  (32 * B_STRIDE)    // 8704
#define B_SEG    (4 * B_CHUNK)      // 34816

// 64-row tiles (shared by rgemm64 and mlp64)
#define A_CHUNK64 (64 * A_STRIDE)   // 5120
#define A_SEG64   (4 * A_CHUNK64)   // 20480
#define SMEM64    (2 * A_SEG64 + 2 * B_SEG)   // 110592 -> 2 CTAs/SM

// ================= relation GEMM: M=64 tiles, 2 CTAs/SM, single-buffered B =======
// mat order: w1 (i=0) -> b1 fp32+bias; rels 0..7 -> hall fp16.
__global__ __launch_bounds__(256, 2) void rgemm_fused64(
    const float* __restrict__ X,
    const bf16* __restrict__ Whi, const bf16* __restrict__ Wlo,
    const float* __restrict__ w1_b,
    __half* __restrict__ hall, float* __restrict__ b1, int n_rows)
{
    extern __shared__ __align__(16) char sm[];
    const uint32_t sA0 = s2u(sm);
    const uint32_t sB0 = sA0 + 2 * A_SEG64;

    const int tid = threadIdx.x, lane = tid & 31, wid = tid >> 5;
    const int wm = wid & 1, wn = wid >> 1;
    const int row0 = blockIdx.x * 64;

    const int br = tid >> 4, bq = tid & 15;
    auto matOf = [&](int i) { return (i == 0) ? 8 : (i - 1); };
    auto loadB = [&](int mat) {
#pragma unroll
        for (int seg = 0; seg < 2; ++seg) {
            const bf16* g = (seg ? Wlo : Whi) + (size_t)mat * 16384;
#pragma unroll
            for (int c = 0; c < 4; ++c) {
                cp16z(sB0 + seg * B_SEG + c * B_CHUNK + br * B_STRIDE + bq * 16,
                      g + (size_t)(c * 32 + br) * 128 + bq * 8, 16);
                cp16z(sB0 + seg * B_SEG + c * B_CHUNK + (br + 16) * B_STRIDE + bq * 16,
                      g + (size_t)(c * 32 + br + 16) * 128 + bq * 8, 16);
            }
        }
    };
    loadB(matOf(0));
    cp_commit();

    // ---- split x tile directly from global: 4 threads/row ----
    {
        const int r = tid >> 2;               // 0..63
        const int c0 = (tid & 3) * 32;
        const int gr = row0 + r;
        const bool ok = gr < n_rows;
#pragma unroll
        for (int j = 0; j < 16; ++j) {
            int col = c0 + j * 2;
            float2 v = ok ? *(const float2*)(X + (size_t)gr * 128 + col)
                          : make_float2(0.f, 0.f);
            bf16 h0 = __float2bfloat16(v.x), h1 = __float2bfloat16(v.y);
            uint32_t o = (col >> 5) * A_CHUNK64 + r * A_STRIDE + (col & 31) * 2;
            *(__nv_bfloat162*)(sm + o) = __nv_bfloat162(h0, h1);
            *(__nv_bfloat162*)(sm + A_SEG64 + o) = __nv_bfloat162(
                __float2bfloat16(v.x - __bfloat162float(h0)),
                __float2bfloat16(v.y - __bfloat162float(h1)));
        }
    }

    float acc[2][4][4];
#pragma unroll
    for (int f = 0; f < 2; ++f)
#pragma unroll
        for (int g = 0; g < 4; ++g)
#pragma unroll
            for (int r = 0; r < 4; ++r) acc[f][g][r] = 0.f;

    const int arow = lane & 15, ahalf = lane >> 4;
    const int blrow = lane & 15, bnc = (lane >> 4) * 8;
    const int tr = lane >> 2, tc = (lane & 3) * 2;

    for (int i = 0; i < 9; ++i) {
        cp_wait<0>();
        __syncthreads();           // B(i) ready; prior epilogue/mma done

        // ---- mma pass over B (single buffer) ----
#pragma unroll
        for (int c = 0; c < 4; ++c) {
#pragma unroll
            for (int s = 0; s < 2; ++s) {
                uint32_t ah[2][4], al[2][4], bh[2][4], bl[2][4];
#pragma unroll
                for (int f = 0; f < 2; ++f) {
                    uint32_t aa = sA0 + c * A_CHUNK64 + (wm * 32 + f * 16 + arow) * A_STRIDE
                                + (s * 2 + ahalf) * 16;
                    ldsm4(aa,           ah[f][0], ah[f][1], ah[f][2], ah[f][3]);
                    ldsm4(aa + A_SEG64, al[f][0], al[f][1], al[f][2], al[f][3]);
                }
#pragma unroll
                for (int g = 0; g < 2; ++g) {
                    uint32_t ba = sB0 + c * B_CHUNK + (s * 16 + blrow) * B_STRIDE
                                + (wn * 32 + g * 16 + bnc) * 2;
                    ldsm4t(ba,         bh[g][0], bh[g][1], bh[g][2], bh[g][3]);
                    ldsm4t(ba + B_SEG, bl[g][0], bl[g][1], bl[g][2], bl[g][3]);
                }
#pragma unroll
                for (int f = 0; f < 2; ++f) {
#pragma unroll
                    for (int g = 0; g < 2; ++g) {
                        mma16816(acc[f][g*2+0][0], acc[f][g*2+0][1], acc[f][g*2+0][2], acc[f][g*2+0][3],
                                 ah[f][0], ah[f][1], ah[f][2], ah[f][3], bh[g][0], bh[g][1]);
                        mma16816(acc[f][g*2+1][0], acc[f][g*2+1][1], acc[f][g*2+1][2], acc[f][g*2+1][3],
                                 ah[f][0], ah[f][1], ah[f][2], ah[f][3], bh[g][2], bh[g][3]);
                        mma16816(acc[f][g*2+0][0], acc[f][g*2+0][1], acc[f][g*2+0][2], acc[f][g*2+0][3],
                                 ah[f][0], ah[f][1], ah[f][2], ah[f][3], bl[g][0], bl[g][1]);
                        mma16816(acc[f][g*2+1][0], acc[f][g*2+1][1], acc[f][g*2+1][2], acc[f][g*2+1][3],
                                 ah[f][0], ah[f][1], ah[f][2], ah[f][3], bl[g][2], bl[g][3]);
                        mma16816(acc[f][g*2+0][0], acc[f][g*2+0][1], acc[f][g*2+0][2], acc[f][g*2+0][3],
                                 al[f][0], al[f][1], al[f][2], al[f][3], bh[g][0], bh[g][1]);
                        mma16816(acc[f][g*2+1][0], acc[f][g*2+1][1], acc[f][g*2+1][2], acc[f][g*2+1][3],
                                 al[f][0], al[f][1], al[f][2], al[f][3], bh[g][2], bh[g][3]);
                    }
                }
            }
        }

        __syncthreads();           // all warps done reading B buffer
        if (i < 8) { loadB(matOf(i + 1)); cp_commit(); }   // overlap with epilogue

        const int mat = matOf(i);
#pragma unroll
        for (int f = 0; f < 2; ++f) {
            int m0 = row0 + wm * 32 + f * 16 + tr;
            int m1 = m0 + 8;
#pragma unroll
            for (int g = 0; g < 4; ++g) {
                int col = wn * 32 + g * 8 + tc;
                if (mat < 8) {
                    __half* C = hall + (size_t)mat * Nn * 128;
                    if (m0 < n_rows)
                        *(__half2*)(C + (size_t)m0 * 128 + col) =
                            __floats2half2_rn(acc[f][g][0], acc[f][g][1]);
                    if (m1 < n_rows)
                        *(__half2*)(C + (size_t)m1 * 128 + col) =
                            __floats2half2_rn(acc[f][g][2], acc[f][g][3]);
                } else {
                    float bb0 = w1_b[col], bb1 = w1_b[col + 1];
                    if (m0 < n_rows) *(float2*)(b1 + (size_t)m0 * 128 + col) =
                        make_float2(acc[f][g][0] + bb0, acc[f][g][1] + bb1);
                    if (m1 < n_rows) *(float2*)(b1 + (size_t)m1 * 128 + col) =
                        make_float2(acc[f][g][2] + bb0, acc[f][g][3] + bb1);
                }
                acc[f][g][0] = acc[f][g][1] = acc[f][g][2] = acc[f][g][3] = 0.f;
            }
        }
    }
}

// ================= fused MLP, 64-row tiles, 2 CTAs/SM (proven R12/R13) ============
__global__ __launch_bounds__(256, 2) void mlp_fused64(
    const float* __restrict__ B1,
    const bf16* __restrict__ M1hi, const bf16* __restrict__ M1lo,
    const bf16* __restrict__ M2hi, const bf16* __restrict__ M2lo,
    const float* __restrict__ m1_b, const float* __restrict__ m2_b,
    float* __restrict__ out, int n_rows)
{
    extern __shared__ __align__(16) char sm[];
    const uint32_t sA0 = s2u(sm);
    const uint32_t sB0 = sA0 + 2 * A_SEG64;

    const int tid = threadIdx.x, lane = tid & 31, wid = tid >> 5;
    const int wm = wid & 1, wn = wid >> 1;
    const int row0 = blockIdx.x * 64;

    const int br = tid >> 4, bq = tid & 15;
    auto loadB = [&](const bf16* Bh, const bf16* Bl) {
#pragma unroll
        for (int seg = 0; seg < 2; ++seg) {
            const bf16* g = seg ? Bl : Bh;
#pragma unroll
            for (int c = 0; c < 4; ++c) {
                cp16z(sB0 + seg * B_SEG + c * B_CHUNK + br * B_STRIDE + bq * 16,
                      g + (size_t)(c * 32 + br) * 128 + bq * 8, 16);
                cp16z(sB0 + seg * B_SEG + c * B_CHUNK + (br + 16) * B_STRIDE + bq * 16,
                      g + (size_t)(c * 32 + br + 16) * 128 + bq * 8, 16);
            }
        }
    };
    loadB(M1hi, M1lo);
    cp_commit();

    {
        const int r = tid >> 2;
        const int c0 = (tid & 3) * 32;
        const int gr = row0 + r;
        const bool ok = gr < n_rows;
#pragma unroll
        for (int j = 0; j < 16; ++j) {
            int col = c0 + j * 2;
            float2 v = ok ? *(const float2*)(B1 + (size_t)gr * 128 + col)
                          : make_float2(0.f, 0.f);
            bf16 h0 = __float2bfloat16(v.x), h1 = __float2bfloat16(v.y);
            uint32_t o = (col >> 5) * A_CHUNK64 + r * A_STRIDE + (col & 31) * 2;
            *(__nv_bfloat162*)(sm + o) = __nv_bfloat162(h0, h1);
            *(__nv_bfloat162*)(sm + A_SEG64 + o) = __nv_bfloat162(
                __float2bfloat16(v.x - __bfloat162float(h0)),
                __float2bfloat16(v.y - __bfloat162float(h1)));
        }
    }
    cp_wait<0>();
    __syncthreads();

    float acc[2][4][4];
#pragma unroll
    for (int f = 0; f < 2; ++f)
#pragma unroll
        for (int g = 0; g < 4; ++g)
#pragma unroll
            for (int r = 0; r < 4; ++r) acc[f][g][r] = 0.f;

    const int arow = lane & 15, ahalf = lane >> 4;
    const int blrow = lane & 15, bnc = (lane >> 4) * 8;
    const int tr = lane >> 2, tc = (lane & 3) * 2;

    auto mma_pass = [&]() {
#pragma unroll
        for (int c = 0; c < 4; ++c) {
#pragma unroll
            for (int s = 0; s < 2; ++s) {
                uint32_t ah[2][4], al[2][4], bh[2][4], bl[2][4];
#pragma unroll
                for (int f = 0; f < 2; ++f) {
                    uint32_t aa = sA0 + c * A_CHUNK64 + (wm * 32 + f * 16 + arow) * A_STRIDE
                                + (s * 2 + ahalf) * 16;
                    ldsm4(aa,           ah[f][0], ah[f][1], ah[f][2], ah[f][3]);
                    ldsm4(aa + A_SEG64, al[f][0], al[f][1], al[f][2], al[f][3]);
                }
#pragma unroll
                for (int g = 0; g < 2; ++g) {
                    uint32_t ba = sB0 + c * B_CHUNK + (s * 16 + blrow) * B_STRIDE
                                + (wn * 32 + g * 16 + bnc) * 2;
                    ldsm4t(ba,         bh[g][0], bh[g][1], bh[g][2], bh[g][3]);
                    ldsm4t(ba + B_SEG, bl[g][0], bl[g][1], bl[g][2], bl[g][3]);
                }
#pragma unroll
                for (int f = 0; f < 2; ++f) {
#pragma unroll
                    for (int g = 0; g < 2; ++g) {
                        mma16816(acc[f][g*2+0][0], acc[f][g*2+0][1], acc[f][g*2+0][2], acc[f][g*2+0][3],
                                 ah[f][0], ah[f][1], ah[f][2], ah[f][3], bh[g][0], bh[g][1]);
                        mma16816(acc[f][g*2+1][0], acc[f][g*2+1][1], acc[f][g*2+1][2], acc[f][g*2+1][3],
                                 ah[f][0], ah[f][1], ah[f][2], ah[f][3], bh[g][2], bh[g][3]);
                        mma16816(acc[f][g*2+0][0], acc[f][g*2+0][1], acc[f][g*2+0][2], acc[f][g*2+0][3],
                                 ah[f][0], ah[f][1], ah[f][2], ah[f][3], bl[g][0], bl[g][1]);
                        mma16816(acc[f][g*2+1][0], acc[f][g*2+1][1], acc[f][g*2+1][2], acc[f][g*2+1][3],
                                 ah[f][0], ah[f][1], ah[f][2], ah[f][3], bl[g][2], bl[g][3]);
                        mma16816(acc[f][g*2+0][0], acc[f][g*2+0][1], acc[f][g*2+0][2], acc[f][g*2+0][3],
                                 al[f][0], al[f][1], al[f][2], al[f][3], bh[g][0], bh[g][1]);
                        mma16816(acc[f][g*2+1][0], acc[f][g*2+1][1], acc[f][g*2+1][2], acc[f][g*2+1][3],
                                 al[f][0], al[f][1], al[f][2], al[f][3], bh[g][2], bh[g][3]);
                    }
                }
            }
        }
    };

    mma_pass();
    __syncthreads();

    loadB(M2hi, M2lo);
    cp_commit();

#pragma unroll
    for (int f = 0; f < 2; ++f) {
        int r0l = wm * 32 + f * 16 + tr;
        int r1l = r0l + 8;
#pragma unroll
        for (int g = 0; g < 4; ++g) {
            int col = wn * 32 + g * 8 + tc;
            float bb0 = m1_b[col], bb1 = m1_b[col + 1];
            float v00 = fmaxf(acc[f][g][0] + bb0, 0.f);
            float v01 = fmaxf(acc[f][g][1] + bb1, 0.f);
            float v10 = fmaxf(acc[f][g][2] + bb0, 0.f);
            float v11 = fmaxf(acc[f][g][3] + bb1, 0.f);
            uint32_t off0 = (col >> 5) * A_CHUNK64 + r0l * A_STRIDE + (col & 31) * 2;
            uint32_t off1 = (col >> 5) * A_CHUNK64 + r1l * A_STRIDE + (col & 31) * 2;
            bf16 h00 = __float2bfloat16(v00), h01 = __float2bfloat16(v01);
            bf16 h10 = __float2bfloat16(v10), h11 = __float2bfloat16(v11);
            *(__nv_bfloat162*)(sm + off0) = __nv_bfloat162(h00, h01);
            *(__nv_bfloat162*)(sm + off1) = __nv_bfloat162(h10, h11);
            *(__nv_bfloat162*)(sm + A_SEG64 + off0) = __nv_bfloat162(
                __float2bfloat16(v00 - __bfloat162float(h00)),
                __float2bfloat16(v01 - __bfloat162float(h01)));
            *(__nv_bfloat162*)(sm + A_SEG64 + off1) = __nv_bfloat162(
                __float2bfloat16(v10 - __bfloat162float(h10)),
                __float2bfloat16(v11 - __bfloat162float(h11)));
            acc[f][g][0] = acc[f][g][1] = acc[f][g][2] = acc[f][g][3] = 0.f;
        }
    }
    cp_wait<0>();
    __syncthreads();

    mma_pass();

#pragma unroll
    for (int f = 0; f < 2; ++f) {
        int m0 = row0 + wm * 32 + f * 16 + tr;
        int m1 = m0 + 8;
#pragma unroll
        for (int g = 0; g < 4; ++g) {
            int col = wn * 32 + g * 8 + tc;
            float bb0 = m2_b[col], bb1 = m2_b[col + 1];
            if (m0 < n_rows)
                *(float2*)(out + (size_t)m0 * 128 + col) =
                    make_float2(acc[f][g][0] + bb0, acc[f][g][1] + bb1);
            if (m1 < n_rows)
                *(float2*)(out + (size_t)m1 * 128 + col) =
                    make_float2(acc[f][g][2] + bb0, acc[f][g][3] + bb1);
        }
    }
}

// ---------------- merged weight split ----------------
__global__ __launch_bounds__(256) void wsplit_kernel(
    const float4* __restrict__ Wrel, const float4* __restrict__ w1W,
    const float4* __restrict__ m1W,  const float4* __restrict__ m2W,
    __nv_bfloat162* __restrict__ Wchi, __nv_bfloat162* __restrict__ Wclo,
    __nv_bfloat162* __restrict__ m1hi, __nv_bfloat162* __restrict__ m1lo,
    __nv_bfloat162* __restrict__ m2hi, __nv_bfloat162* __restrict__ m2lo)
{
    int i = blockIdx.x * 256 + threadIdx.x;
    if (i >= 11 * 4096) return;
    const int mat = i >> 12, local = i & 4095;
    const float4* in;
    __nv_bfloat162 *hi, *lo;
    if (mat < 8)       { in = Wrel + i;    hi = Wchi + i * 2;                  lo = Wclo + i * 2; }
    else if (mat == 8) { in = w1W + local; hi = Wchi + (8 * 4096 + local) * 2; lo = Wclo + (8 * 4096 + local) * 2; }
    else if (mat == 9) { in = m1W + local; hi = m1hi + local * 2;              lo = m1lo + local * 2; }
    else               { in = m2W + local; hi = m2hi + local * 2;              lo = m2lo + local * 2; }
    float4 v = *in;
    bf16 hx = __float2bfloat16(v.x), hy = __float2bfloat16(v.y);
    bf16 hz = __float2bfloat16(v.z), hw = __float2bfloat16(v.w);
    hi[0] = __nv_bfloat162(hx, hy);
    hi[1] = __nv_bfloat162(hz, hw);
    lo[0] = __nv_bfloat162(__float2bfloat16(v.x - __bfloat162float(hx)),
                           __float2bfloat16(v.y - __bfloat162float(hy)));
    lo[1] = __nv_bfloat162(__float2bfloat16(v.z - __bfloat162float(hz)),
                           __float2bfloat16(v.w - __bfloat162float(hw)));
}

// ---------------- edge scatter: 4 edges/warp, fp16 hall reads (proven R13) -------
__global__ __launch_bounds__(256) void edge_scatter(
    const __half* __restrict__ hall,
    const int* __restrict__ src, const int* __restrict__ dst,
    const int* __restrict__ etype, float* __restrict__ agg)
{
    const int w    = (blockIdx.x * 256 + threadIdx.x) >> 5;
    const int lane = threadIdx.x & 31;
    const int e0   = w * 4;
    if (e0 >= Ee) return;

    int s[4], d[4], t[4];
#pragma unroll
    for (int i = 0; i < 4; ++i) {
        s[i] = __ldg(src + e0 + i);
        d[i] = __ldg(dst + e0 + i);
        t[i] = __ldg(etype + e0 + i);
    }
    __half2 v[4][2];
#pragma unroll
    for (int i = 0; i < 4; ++i) {
        const __half2* row = (const __half2*)(hall + ((size_t)t[i] * Nn + s[i]) * 128);
        uint2 raw = *(const uint2*)(row + lane * 2);
        v[i][0] = *(__half2*)&raw.x;
        v[i][1] = *(__half2*)&raw.y;
    }
#pragma unroll
    for (int i = 0; i < 4; ++i) {
        float2 a = __half22float2(v[i][0]);
        float2 b = __half22float2(v[i][1]);
        float* o = agg + (size_t)d[i] * 128 + lane * 4;
        asm volatile("red.global.add.v4.f32 [%0], {%1,%2,%3,%4};"
                     :: "l"(o), "f"(a.x), "f"(a.y), "f"(b.x), "f"(b.y) : "memory");
    }
}

// ---------------- launch ----------------
extern "C" void kernel_launch(void* const* d_in, const int* in_sizes, int n_in,
                              void* d_out, int out_size)
{
    const float* x     = (const float*)d_in[0];
    const int*   src   = (const int*)  d_in[1];
    const int*   dst   = (const int*)  d_in[2];
    const int*   etype = (const int*)  d_in[3];
    const float* W_rel = (const float*)d_in[4];
    const float* w1_W  = (const float*)d_in[5];
    const float* w1_b  = (const float*)d_in[6];
    const float* m1_W  = (const float*)d_in[7];
    const float* m1_b  = (const float*)d_in[8];
    const float* m2_W  = (const float*)d_in[9];
    const float* m2_b  = (const float*)d_in[10];
    float* out = (float*)d_out;

    __half* hall;
    float* b1;
    bf16 *Wchi, *Wclo, *m1hi, *m1lo, *m2hi, *m2lo;
    cudaGetSymbolAddress((void**)&hall, g_hall);
    cudaGetSymbolAddress((void**)&b1,   g_b1);
    cudaGetSymbolAddress((void**)&Wchi, g_Wchi);
    cudaGetSymbolAddress((void**)&Wclo, g_Wclo);
    cudaGetSymbolAddress((void**)&m1hi, g_m1hi);
    cudaGetSymbolAddress((void**)&m1lo, g_m1lo);
    cudaGetSymbolAddress((void**)&m2hi, g_m2hi);
    cudaGetSymbolAddress((void**)&m2lo, g_m2lo);

    cudaFuncSetAttribute(rgemm_fused64, cudaFuncAttributeMaxDynamicSharedMemorySize, SMEM64);
    cudaFuncSetAttribute(mlp_fused64,   cudaFuncAttributeMaxDynamicSharedMemorySize, SMEM64);

    const int nTiles64 = (Nn + 63) / 64;    // 782
    const int sgrid    = (Ee + 31) / 32;    // 4 edges/warp -> 20000 blocks

    wsplit_kernel<<<(11 * 4096 + 255) / 256, 256>>>(
        (const float4*)W_rel, (const float4*)w1_W,
        (const float4*)m1_W, (const float4*)m2_W,
        (__nv_bfloat162*)Wchi, (__nv_bfloat162*)Wclo,
        (__nv_bfloat162*)m1hi, (__nv_bfloat162*)m1lo,
        (__nv_bfloat162*)m2hi, (__nv_bfloat162*)m2lo);

    // hall[r] = x @ W_rel[r] (fp16); b1 = x @ w1 + w1_b (fp32)  — 2 CTAs/SM
    rgemm_fused64<<<nTiles64, 256, SMEM64>>>(x, Wchi, Wclo, w1_b, hall, b1, Nn);

    // b1[dst] += hall[etype, src]
    edge_scatter<<<sgrid, 256>>>(hall, src, dst, etype, b1);

    // out = relu(b1 @ m1 + b) @ m2 + b
    mlp_fused64<<<nTiles64, 256, SMEM64>>>(b1, m1hi, m1lo, m2hi, m2lo,
                                           m1_b, m2_b, out, Nn);
}

// round 15
// speedup vs baseline: 1.0083x; 1.0083x over previous
#include <cuda_runtime.h>
#include <cuda_bf16.h>
#include <cuda_fp16.h>
#include <cstdint>

#define Nn 50000
#define Ee 640000
#define Rr 8
typedef __nv_bfloat16 bf16;

// ---------------- scratch ----------------
__device__ __half g_hall[(size_t)Rr * Nn * 128];   // fp16 messages (scatter feed)
__device__ float  g_b1[(size_t)Nn * 128];
__device__ bf16   g_Wchi[9 * 128 * 128], g_Wclo[9 * 128 * 128];   // 8 rels + w1
__device__ bf16   g_m1hi[128 * 128], g_m1lo[128 * 128];
__device__ bf16   g_m2hi[128 * 128], g_m2lo[128 * 128];

// ---------------- asm helpers ----------------
__device__ __forceinline__ uint32_t s2u(const void* p) {
    return (uint32_t)__cvta_generic_to_shared(p);
}
__device__ __forceinline__ void cp16z(uint32_t d, const void* s, int sz) {
    asm volatile("cp.async.cg.shared.global [%0],[%1],16,%2;\n" :: "r"(d), "l"(s), "r"(sz));
}
__device__ __forceinline__ void cp_commit() { asm volatile("cp.async.commit_group;\n"); }
template<int N> __device__ __forceinline__ void cp_wait() {
    asm volatile("cp.async.wait_group %0;\n" :: "n"(N));
}
__device__ __forceinline__ void ldsm4(uint32_t a, uint32_t& r0, uint32_t& r1,
                                      uint32_t& r2, uint32_t& r3) {
    asm volatile("ldmatrix.sync.aligned.m8n8.x4.shared.b16 {%0,%1,%2,%3}, [%4];"
                 : "=r"(r0), "=r"(r1), "=r"(r2), "=r"(r3) : "r"(a));
}
__device__ __forceinline__ void ldsm4t(uint32_t a, uint32_t& r0, uint32_t& r1,
                                       uint32_t& r2, uint32_t& r3) {
    asm volatile("ldmatrix.sync.aligned.m8n8.x4.trans.shared.b16 {%0,%1,%2,%3}, [%4];"
                 : "=r"(r0), "=r"(r1), "=r"(r2), "=r"(r3) : "r"(a));
}
__device__ __forceinline__ void mma16816(float& d0, float& d1, float& d2, float& d3,
                                         uint32_t a0, uint32_t a1, uint32_t a2, uint32_t a3,
                                         uint32_t b0, uint32_t b1) {
    asm volatile(
        "mma.sync.aligned.m16n8k16.row.col.f32.bf16.bf16.f32 "
        "{%0,%1,%2,%3}, {%4,%5,%6,%7}, {%8,%9}, {%0,%1,%2,%3};"
        : "+f"(d0), "+f"(d1), "+f"(d2), "+f"(d3)
        : "r"(a0), "r"(a1), "r"(a2), "r"(a3), "r"(b0), "r"(b1));
}

#define A_STRIDE 80
#define A_CHUNK  (128 * A_STRIDE)   // 10240
#define A_SEG    (4 * A_CHUNK)      // 40960
#define B_STRIDE 272
#define B_CHUNK  (32 * B_STRIDE)    // 8704
#define B_SEG    (4 * B_CHUNK)      // 34816
#define B_BUF    (2 * B_SEG)        // 69632
#define FUSED_SMEM (2 * A_SEG + 2 * B_BUF)            // 221184

// mlp64: 64-row tiles
#define A_CHUNK64 (64 * A_STRIDE)   // 5120
#define A_SEG64   (4 * A_CHUNK64)   // 20480
#define MLP64_SMEM (2 * A_SEG64 + 2 * B_SEG)          // 110592 -> 2 CTAs/SM

// ================= fused relation GEMM (R13 proven; w1 first; hall fp16) =========
__global__ __launch_bounds__(256, 1) void rgemm_fused(
    const float* __restrict__ X,
    const bf16* __restrict__ Whi, const bf16* __restrict__ Wlo,
    const float* __restrict__ w1_b,
    __half* __restrict__ hall, float* __restrict__ b1, int n_rows)
{
    extern __shared__ __align__(16) char sm[];
    const uint32_t sA0 = s2u(sm);
    const uint32_t sB0 = sA0 + 2 * A_SEG;

    const int tid = threadIdx.x, lane = tid & 31, wid = tid >> 5;
    const int wm = wid & 1, wn = wid >> 1;
    const int row0 = blockIdx.x * 128;

    // ---- stage fp32 x tile into sB area, split to sA hi/lo ----
    {
        const int r = tid >> 1, h = tid & 1;
        const int gr = row0 + r;
#pragma unroll
        for (int i = 0; i < 16; ++i)
            cp16z(sB0 + r * 512 + h * 256 + i * 16,
                  X + (size_t)gr * 128 + h * 64 + i * 4, gr < n_rows ? 16 : 0);
        cp_commit();
        cp_wait<0>();
        __syncthreads();
#pragma unroll
        for (int j = 0; j < 32; ++j) {
            int col = h * 64 + j * 2;
            float2 v = *(const float2*)(sm + 2 * A_SEG + r * 512 + col * 4);
            bf16 h0 = __float2bfloat16(v.x), h1 = __float2bfloat16(v.y);
            uint32_t o = (col >> 5) * A_CHUNK + r * A_STRIDE + (col & 31) * 2;
            *(__nv_bfloat162*)(sm + o) = __nv_bfloat162(h0, h1);
            *(__nv_bfloat162*)(sm + A_SEG + o) = __nv_bfloat162(
                __float2bfloat16(v.x - __bfloat162float(h0)),
                __float2bfloat16(v.y - __bfloat162float(h1)));
        }
        __syncthreads();
    }

    const int br = tid >> 4, bq = tid & 15;
    auto matOf = [&](int i) { return (i == 0) ? 8 : (i - 1); };   // w1 first, then rels
    auto loadB = [&](int mat, int buf) {
#pragma unroll
        for (int seg = 0; seg < 2; ++seg) {
            const bf16* g = (seg ? Wlo : Whi) + (size_t)mat * 16384;
#pragma unroll
            for (int c = 0; c < 4; ++c) {
                cp16z(sB0 + buf * B_BUF + seg * B_SEG + c * B_CHUNK + br * B_STRIDE + bq * 16,
                      g + (size_t)(c * 32 + br) * 128 + bq * 8, 16);
                cp16z(sB0 + buf * B_BUF + seg * B_SEG + c * B_CHUNK + (br + 16) * B_STRIDE + bq * 16,
                      g + (size_t)(c * 32 + br + 16) * 128 + bq * 8, 16);
            }
        }
    };
    loadB(matOf(0), 0);
    cp_commit();

    float acc[4][4][4];
#pragma unroll
    for (int f = 0; f < 4; ++f)
#pragma unroll
        for (int g = 0; g < 4; ++g)
#pragma unroll
            for (int r = 0; r < 4; ++r) acc[f][g][r] = 0.f;

    const int arow = lane & 15, ahalf = lane >> 4;
    const int blrow = lane & 15, bnc = (lane >> 4) * 8;
    const int tr = lane >> 2, tc = (lane & 3) * 2;

    for (int i = 0; i < 9; ++i) {
        const int buf = i & 1;
        cp_wait<0>();
        __syncthreads();
        if (i < 8) { loadB(matOf(i + 1), buf ^ 1); cp_commit(); }

        const uint32_t bB = sB0 + buf * B_BUF;
#pragma unroll
        for (int c = 0; c < 4; ++c) {
#pragma unroll
            for (int s = 0; s < 2; ++s) {
                uint32_t ah[4][4], al[4][4], bh[2][4], bl[2][4];
#pragma unroll
                for (int f = 0; f < 4; ++f) {
                    uint32_t aa = sA0 + c * A_CHUNK + (wm * 64 + f * 16 + arow) * A_STRIDE
                                + (s * 2 + ahalf) * 16;
                    ldsm4(aa,         ah[f][0], ah[f][1], ah[f][2], ah[f][3]);
                    ldsm4(aa + A_SEG, al[f][0], al[f][1], al[f][2], al[f][3]);
                }
#pragma unroll
                for (int g = 0; g < 2; ++g) {
                    uint32_t ba = bB + c * B_CHUNK + (s * 16 + blrow) * B_STRIDE
                                + (wn * 32 + g * 16 + bnc) * 2;
                    ldsm4t(ba,         bh[g][0], bh[g][1], bh[g][2], bh[g][3]);
                    ldsm4t(ba + B_SEG, bl[g][0], bl[g][1], bl[g][2], bl[g][3]);
                }
#pragma unroll
                for (int f = 0; f < 4; ++f) {
#pragma unroll
                    for (int g = 0; g < 2; ++g) {
                        mma16816(acc[f][g*2+0][0], acc[f][g*2+0][1], acc[f][g*2+0][2], acc[f][g*2+0][3],
                                 ah[f][0], ah[f][1], ah[f][2], ah[f][3], bh[g][0], bh[g][1]);
                        mma16816(acc[f][g*2+1][0], acc[f][g*2+1][1], acc[f][g*2+1][2], acc[f][g*2+1][3],
                                 ah[f][0], ah[f][1], ah[f][2], ah[f][3], bh[g][2], bh[g][3]);
                        mma16816(acc[f][g*2+0][0], acc[f][g*2+0][1], acc[f][g*2+0][2], acc[f][g*2+0][3],
                                 ah[f][0], ah[f][1], ah[f][2], ah[f][3], bl[g][0], bl[g][1]);
                        mma16816(acc[f][g*2+1][0], acc[f][g*2+1][1], acc[f][g*2+1][2], acc[f][g*2+1][3],
                                 ah[f][0], ah[f][1], ah[f][2], ah[f][3], bl[g][2], bl[g][3]);
                        mma16816(acc[f][g*2+0][0], acc[f][g*2+0][1], acc[f][g*2+0][2], acc[f][g*2+0][3],
                                 al[f][0], al[f][1], al[f][2], al[f][3], bh[g][0], bh[g][1]);
                        mma16816(acc[f][g*2+1][0], acc[f][g*2+1][1], acc[f][g*2+1][2], acc[f][g*2+1][3],
                                 al[f][0], al[f][1], al[f][2], al[f][3], bh[g][2], bh[g][3]);
                    }
                }
            }
        }

        const int mat = matOf(i);
#pragma unroll
        for (int f = 0; f < 4; ++f) {
            int m0 = row0 + wm * 64 + f * 16 + tr;
            int m1 = m0 + 8;
#pragma unroll
            for (int g = 0; g < 4; ++g) {
                int col = wn * 32 + g * 8 + tc;
                if (mat < 8) {
                    __half* C = hall + (size_t)mat * Nn * 128;
                    if (m0 < n_rows)
                        *(__half2*)(C + (size_t)m0 * 128 + col) =
                            __floats2half2_rn(acc[f][g][0], acc[f][g][1]);
                    if (m1 < n_rows)
                        *(__half2*)(C + (size_t)m1 * 128 + col) =
                            __floats2half2_rn(acc[f][g][2], acc[f][g][3]);
                } else {
                    float bb0 = w1_b[col], bb1 = w1_b[col + 1];
                    if (m0 < n_rows) *(float2*)(b1 + (size_t)m0 * 128 + col) =
                        make_float2(acc[f][g][0] + bb0, acc[f][g][1] + bb1);
                    if (m1 < n_rows) *(float2*)(b1 + (size_t)m1 * 128 + col) =
                        make_float2(acc[f][g][2] + bb0, acc[f][g][3] + bb1);
                }
                acc[f][g][0] = acc[f][g][1] = acc[f][g][2] = acc[f][g][3] = 0.f;
            }
        }
    }
}

// ================= fused MLP, 64-row tiles, 2 CTAs/SM (R13 proven) ================
__global__ __launch_bounds__(256, 2) void mlp_fused64(
    const float* __restrict__ B1,
    const bf16* __restrict__ M1hi, const bf16* __restrict__ M1lo,
    const bf16* __restrict__ M2hi, const bf16* __restrict__ M2lo,
    const float* __restrict__ m1_b, const float* __restrict__ m2_b,
    float* __restrict__ out, int n_rows)
{
    extern __shared__ __align__(16) char sm[];
    const uint32_t sA0 = s2u(sm);
    const uint32_t sB0 = sA0 + 2 * A_SEG64;

    const int tid = threadIdx.x, lane = tid & 31, wid = tid >> 5;
    const int wm = wid & 1, wn = wid >> 1;
    const int row0 = blockIdx.x * 64;

    const int br = tid >> 4, bq = tid & 15;
    auto loadB = [&](const bf16* Bh, const bf16* Bl) {
#pragma unroll
        for (int seg = 0; seg < 2; ++seg) {
            const bf16* g = seg ? Bl : Bh;
#pragma unroll
            for (int c = 0; c < 4; ++c) {
                cp16z(sB0 + seg * B_SEG + c * B_CHUNK + br * B_STRIDE + bq * 16,
                      g + (size_t)(c * 32 + br) * 128 + bq * 8, 16);
                cp16z(sB0 + seg * B_SEG + c * B_CHUNK + (br + 16) * B_STRIDE + bq * 16,
                      g + (size_t)(c * 32 + br + 16) * 128 + bq * 8, 16);
            }
        }
    };
    loadB(M1hi, M1lo);
    cp_commit();

    // ---- split b1 tile directly from global: 4 threads/row ----
    {
        const int r = tid >> 2;
        const int c0 = (tid & 3) * 32;
        const int gr = row0 + r;
        const bool ok = gr < n_rows;
#pragma unroll
        for (int j = 0; j < 16; ++j) {
            int col = c0 + j * 2;
            float2 v = ok ? *(const float2*)(B1 + (size_t)gr * 128 + col)
                          : make_float2(0.f, 0.f);
            bf16 h0 = __float2bfloat16(v.x), h1 = __float2bfloat16(v.y);
            uint32_t o = (col >> 5) * A_CHUNK64 + r * A_STRIDE + (col & 31) * 2;
            *(__nv_bfloat162*)(sm + o) = __nv_bfloat162(h0, h1);
            *(__nv_bfloat162*)(sm + A_SEG64 + o) = __nv_bfloat162(
                __float2bfloat16(v.x - __bfloat162float(h0)),
                __float2bfloat16(v.y - __bfloat162float(h1)));
        }
    }
    cp_wait<0>();
    __syncthreads();

    float acc[2][4][4];
#pragma unroll
    for (int f = 0; f < 2; ++f)
#pragma unroll
        for (int g = 0; g < 4; ++g)
#pragma unroll
            for (int r = 0; r < 4; ++r) acc[f][g][r] = 0.f;

    const int arow = lane & 15, ahalf = lane >> 4;
    const int blrow = lane & 15, bnc = (lane >> 4) * 8;
    const int tr = lane >> 2, tc = (lane & 3) * 2;

    auto mma_pass = [&]() {
#pragma unroll
        for (int c = 0; c < 4; ++c) {
#pragma unroll
            for (int s = 0; s < 2; ++s) {
                uint32_t ah[2][4], al[2][4], bh[2][4], bl[2][4];
#pragma unroll
                for (int f = 0; f < 2; ++f) {
                    uint32_t aa = sA0 + c * A_CHUNK64 + (wm * 32 + f * 16 + arow) * A_STRIDE
                                + (s * 2 + ahalf) * 16;
                    ldsm4(aa,           ah[f][0], ah[f][1], ah[f][2], ah[f][3]);
                    ldsm4(aa + A_SEG64, al[f][0], al[f][1], al[f][2], al[f][3]);
                }
#pragma unroll
                for (int g = 0; g < 2; ++g) {
                    uint32_t ba = sB0 + c * B_CHUNK + (s * 16 + blrow) * B_STRIDE
                                + (wn * 32 + g * 16 + bnc) * 2;
                    ldsm4t(ba,         bh[g][0], bh[g][1], bh[g][2], bh[g][3]);
                    ldsm4t(ba + B_SEG, bl[g][0], bl[g][1], bl[g][2], bl[g][3]);
                }
#pragma unroll
                for (int f = 0; f < 2; ++f) {
#pragma unroll
                    for (int g = 0; g < 2; ++g) {
                        mma16816(acc[f][g*2+0][0], acc[f][g*2+0][1], acc[f][g*2+0][2], acc[f][g*2+0][3],
                                 ah[f][0], ah[f][1], ah[f][2], ah[f][3], bh[g][0], bh[g][1]);
                        mma16816(acc[f][g*2+1][0], acc[f][g*2+1][1], acc[f][g*2+1][2], acc[f][g*2+1][3],
                                 ah[f][0], ah[f][1], ah[f][2], ah[f][3], bh[g][2], bh[g][3]);
                        mma16816(acc[f][g*2+0][0], acc[f][g*2+0][1], acc[f][g*2+0][2], acc[f][g*2+0][3],
                                 ah[f][0], ah[f][1], ah[f][2], ah[f][3], bl[g][0], bl[g][1]);
                        mma16816(acc[f][g*2+1][0], acc[f][g*2+1][1], acc[f][g*2+1][2], acc[f][g*2+1][3],
                                 ah[f][0], ah[f][1], ah[f][2], ah[f][3], bl[g][2], bl[g][3]);
                        mma16816(acc[f][g*2+0][0], acc[f][g*2+0][1], acc[f][g*2+0][2], acc[f][g*2+0][3],
                                 al[f][0], al[f][1], al[f][2], al[f][3], bh[g][0], bh[g][1]);
                        mma16816(acc[f][g*2+1][0], acc[f][g*2+1][1], acc[f][g*2+1][2], acc[f][g*2+1][3],
                                 al[f][0], al[f][1], al[f][2], al[f][3], bh[g][2], bh[g][3]);
                    }
                }
            }
        }
    };

    mma_pass();
    __syncthreads();

    loadB(M2hi, M2lo);
    cp_commit();

#pragma unroll
    for (int f = 0; f < 2; ++f) {
        int r0l = wm * 32 + f * 16 + tr;
        int r1l = r0l + 8;
#pragma unroll
        for (int g = 0; g < 4; ++g) {
            int col = wn * 32 + g * 8 + tc;
            float bb0 = m1_b[col], bb1 = m1_b[col + 1];
            float v00 = fmaxf(acc[f][g][0] + bb0, 0.f);
            float v01 = fmaxf(acc[f][g][1] + bb1, 0.f);
            float v10 = fmaxf(acc[f][g][2] + bb0, 0.f);
            float v11 = fmaxf(acc[f][g][3] + bb1, 0.f);
            uint32_t off0 = (col >> 5) * A_CHUNK64 + r0l * A_STRIDE + (col & 31) * 2;
            uint32_t off1 = (col >> 5) * A_CHUNK64 + r1l * A_STRIDE + (col & 31) * 2;
            bf16 h00 = __float2bfloat16(v00), h01 = __float2bfloat16(v01);
            bf16 h10 = __float2bfloat16(v10), h11 = __float2bfloat16(v11);
            *(__nv_bfloat162*)(sm + off0) = __nv_bfloat162(h00, h01);
            *(__nv_bfloat162*)(sm + off1) = __nv_bfloat162(h10, h11);
            *(__nv_bfloat162*)(sm + A_SEG64 + off0) = __nv_bfloat162(
                __float2bfloat16(v00 - __bfloat162float(h00)),
                __float2bfloat16(v01 - __bfloat162float(h01)));
            *(__nv_bfloat162*)(sm + A_SEG64 + off1) = __nv_bfloat162(
                __float2bfloat16(v10 - __bfloat162float(h10)),
                __float2bfloat16(v11 - __bfloat162float(h11)));
            acc[f][g][0] = acc[f][g][1] = acc[f][g][2] = acc[f][g][3] = 0.f;
        }
    }
    cp_wait<0>();
    __syncthreads();

    mma_pass();

#pragma unroll
    for (int f = 0; f < 2; ++f) {
        int m0 = row0 + wm * 32 + f * 16 + tr;
        int m1 = m0 + 8;
#pragma unroll
        for (int g = 0; g < 4; ++g) {
            int col = wn * 32 + g * 8 + tc;
            float bb0 = m2_b[col], bb1 = m2_b[col + 1];
            if (m0 < n_rows)
                *(float2*)(out + (size_t)m0 * 128 + col) =
                    make_float2(acc[f][g][0] + bb0, acc[f][g][1] + bb1);
            if (m1 < n_rows)
                *(float2*)(out + (size_t)m1 * 128 + col) =
                    make_float2(acc[f][g][2] + bb0, acc[f][g][3] + bb1);
        }
    }
}

// ---------------- merged weight split ----------------
__global__ __launch_bounds__(256) void wsplit_kernel(
    const float4* __restrict__ Wrel, const float4* __restrict__ w1W,
    const float4* __restrict__ m1W,  const float4* __restrict__ m2W,
    __nv_bfloat162* __restrict__ Wchi, __nv_bfloat162* __restrict__ Wclo,
    __nv_bfloat162* __restrict__ m1hi, __nv_bfloat162* __restrict__ m1lo,
    __nv_bfloat162* __restrict__ m2hi, __nv_bfloat162* __restrict__ m2lo)
{
    int i = blockIdx.x * 256 + threadIdx.x;
    if (i >= 11 * 4096) return;
    const int mat = i >> 12, local = i & 4095;
    const float4* in;
    __nv_bfloat162 *hi, *lo;
    if (mat < 8)       { in = Wrel + i;    hi = Wchi + i * 2;                  lo = Wclo + i * 2; }
    else if (mat == 8) { in = w1W + local; hi = Wchi + (8 * 4096 + local) * 2; lo = Wclo + (8 * 4096 + local) * 2; }
    else if (mat == 9) { in = m1W + local; hi = m1hi + local * 2;              lo = m1lo + local * 2; }
    else               { in = m2W + local; hi = m2hi + local * 2;              lo = m2lo + local * 2; }
    float4 v = *in;
    bf16 hx = __float2bfloat16(v.x), hy = __float2bfloat16(v.y);
    bf16 hz = __float2bfloat16(v.z), hw = __float2bfloat16(v.w);
    hi[0] = __nv_bfloat162(hx, hy);
    hi[1] = __nv_bfloat162(hz, hw);
    lo[0] = __nv_bfloat162(__float2bfloat16(v.x - __bfloat162float(hx)),
                           __float2bfloat16(v.y - __bfloat162float(hy)));
    lo[1] = __nv_bfloat162(__float2bfloat16(v.z - __bfloat162float(hz)),
                           __float2bfloat16(v.w - __bfloat162float(hw)));
}

// ---------------- edge scatter: 4 edges/warp, fp16 hall reads (R13 proven) -------
__global__ __launch_bounds__(256) void edge_scatter(
    const __half* __restrict__ hall,
    const int* __restrict__ src, const int* __restrict__ dst,
    const int* __restrict__ etype, float* __restrict__ agg)
{
    const int w    = (blockIdx.x * 256 + threadIdx.x) >> 5;
    const int lane = threadIdx.x & 31;
    const int e0   = w * 4;
    if (e0 >= Ee) return;

    int s[4], d[4], t[4];
#pragma unroll
    for (int i = 0; i < 4; ++i) {
        s[i] = __ldg(src + e0 + i);
        d[i] = __ldg(dst + e0 + i);
        t[i] = __ldg(etype + e0 + i);
    }
    __half2 v[4][2];
#pragma unroll
    for (int i = 0; i < 4; ++i) {
        const __half2* row = (const __half2*)(hall + ((size_t)t[i] * Nn + s[i]) * 128);
        uint2 raw = *(const uint2*)(row + lane * 2);
        v[i][0] = *(__half2*)&raw.x;
        v[i][1] = *(__half2*)&raw.y;
    }
#pragma unroll
    for (int i = 0; i < 4; ++i) {
        float2 a = __half22float2(v[i][0]);
        float2 b = __half22float2(v[i][1]);
        float* o = agg + (size_t)d[i] * 128 + lane * 4;
        asm volatile("red.global.add.v4.f32 [%0], {%1,%2,%3,%4};"
                     :: "l"(o), "f"(a.x), "f"(a.y), "f"(b.x), "f"(b.y) : "memory");
    }
}

// ---------------- launch ----------------
extern "C" void kernel_launch(void* const* d_in, const int* in_sizes, int n_in,
                              void* d_out, int out_size)
{
    const float* x     = (const float*)d_in[0];
    const int*   src   = (const int*)  d_in[1];
    const int*   dst   = (const int*)  d_in[2];
    const int*   etype = (const int*)  d_in[3];
    const float* W_rel = (const float*)d_in[4];
    const float* w1_W  = (const float*)d_in[5];
    const float* w1_b  = (const float*)d_in[6];
    const float* m1_W  = (const float*)d_in[7];
    const float* m1_b  = (const float*)d_in[8];
    const float* m2_W  = (const float*)d_in[9];
    const float* m2_b  = (const float*)d_in[10];
    float* out = (float*)d_out;

    __half* hall;
    float* b1;
    bf16 *Wchi, *Wclo, *m1hi, *m1lo, *m2hi, *m2lo;
    cudaGetSymbolAddress((void**)&hall, g_hall);
    cudaGetSymbolAddress((void**)&b1,   g_b1);
    cudaGetSymbolAddress((void**)&Wchi, g_Wchi);
    cudaGetSymbolAddress((void**)&Wclo, g_Wclo);
    cudaGetSymbolAddress((void**)&m1hi, g_m1hi);
    cudaGetSymbolAddress((void**)&m1lo, g_m1lo);
    cudaGetSymbolAddress((void**)&m2hi, g_m2hi);
    cudaGetSymbolAddress((void**)&m2lo, g_m2lo);

    cudaFuncSetAttribute(rgemm_fused, cudaFuncAttributeMaxDynamicSharedMemorySize, FUSED_SMEM);
    cudaFuncSetAttribute(mlp_fused64, cudaFuncAttributeMaxDynamicSharedMemorySize, MLP64_SMEM);

    const int nTiles   = (Nn + 127) / 128;  // 391
    const int nTiles64 = (Nn + 63) / 64;    // 782
    const int sgrid    = (Ee + 31) / 32;    // 4 edges/warp -> 20000 blocks

    wsplit_kernel<<<(11 * 4096 + 255) / 256, 256>>>(
        (const float4*)W_rel, (const float4*)w1_W,
        (const float4*)m1_W, (const float4*)m2_W,
        (__nv_bfloat162*)Wchi, (__nv_bfloat162*)Wclo,
        (__nv_bfloat162*)m1hi, (__nv_bfloat162*)m1lo,
        (__nv_bfloat162*)m2hi, (__nv_bfloat162*)m2lo);

    // hall[r] = x @ W_rel[r] (fp16); b1 = x @ w1 + w1_b (fp32)
    rgemm_fused<<<nTiles, 256, FUSED_SMEM>>>(x, Wchi, Wclo, w1_b, hall, b1, Nn);

    // b1[dst] += hall[etype, src]
    edge_scatter<<<sgrid, 256>>>(hall, src, dst, etype, b1);

    // out = relu(b1 @ m1 + b) @ m2 + b
    mlp_fused64<<<nTiles64, 256, MLP64_SMEM>>>(b1, m1hi, m1lo, m2hi, m2lo,
                                               m1_b, m2_b, out, Nn);
}

// round 16
// speedup vs baseline: 1.2249x; 1.2148x over previous
#include <cuda_runtime.h>
#include <cuda_fp16.h>
#include <cstdint>

#define Nn 50000
#define Ee 640000
#define Rr 8
typedef __half f16;

// ---------------- scratch ----------------
__device__ f16   g_hall[(size_t)Rr * Nn * 128];   // fp16 messages
__device__ float g_b1[(size_t)Nn * 128];
__device__ f16   g_Wc[9 * 128 * 128];             // 8 rels + w1, single fp16
__device__ f16   g_m1[128 * 128], g_m2[128 * 128];

// ---------------- asm helpers ----------------
__device__ __forceinline__ uint32_t s2u(const void* p) {
    return (uint32_t)__cvta_generic_to_shared(p);
}
__device__ __forceinline__ void cp16z(uint32_t d, const void* s, int sz) {
    asm volatile("cp.async.cg.shared.global [%0],[%1],16,%2;\n" :: "r"(d), "l"(s), "r"(sz));
}
__device__ __forceinline__ void cp_commit() { asm volatile("cp.async.commit_group;\n"); }
template<int N> __device__ __forceinline__ void cp_wait() {
    asm volatile("cp.async.wait_group %0;\n" :: "n"(N));
}
__device__ __forceinline__ void ldsm4(uint32_t a, uint32_t& r0, uint32_t& r1,
                                      uint32_t& r2, uint32_t& r3) {
    asm volatile("ldmatrix.sync.aligned.m8n8.x4.shared.b16 {%0,%1,%2,%3}, [%4];"
                 : "=r"(r0), "=r"(r1), "=r"(r2), "=r"(r3) : "r"(a));
}
__device__ __forceinline__ void ldsm4t(uint32_t a, uint32_t& r0, uint32_t& r1,
                                       uint32_t& r2, uint32_t& r3) {
    asm volatile("ldmatrix.sync.aligned.m8n8.x4.trans.shared.b16 {%0,%1,%2,%3}, [%4];"
                 : "=r"(r0), "=r"(r1), "=r"(r2), "=r"(r3) : "r"(a));
}
__device__ __forceinline__ void mma16816h(float& d0, float& d1, float& d2, float& d3,
                                          uint32_t a0, uint32_t a1, uint32_t a2, uint32_t a3,
                                          uint32_t b0, uint32_t b1) {
    asm volatile(
        "mma.sync.aligned.m16n8k16.row.col.f32.f16.f16.f32 "
        "{%0,%1,%2,%3}, {%4,%5,%6,%7}, {%8,%9}, {%0,%1,%2,%3};"
        : "+f"(d0), "+f"(d1), "+f"(d2), "+f"(d3)
        : "r"(a0), "r"(a1), "r"(a2), "r"(a3), "r"(b0), "r"(b1));
}

#define A_STRIDE 80
#define A_CHUNK  (128 * A_STRIDE)   // 10240
#define A_SEG    (4 * A_CHUNK)      // 40960
#define B_STRIDE 272
#define B_CHUNK  (32 * B_STRIDE)    // 8704
#define B_SEG    (4 * B_CHUNK)      // 34816 (single fp16 weight tile)
#define FUSED_SMEM (2 * A_SEG + 2 * B_SEG)   // 151552 (A hi/lo + B double buffer)

// mlp64: 64-row tiles
#define A_CHUNK64 (64 * A_STRIDE)   // 5120
#define A_SEG64   (4 * A_CHUNK64)   // 20480
#define MLP64_SMEM (2 * A_SEG64 + B_SEG)     // 75776 -> 2+ CTAs/SM

// ================= fused relation GEMM: fp16 2-pass (Ahi·B + Alo·B) ==============
// mat order: w1 (i=0) -> b1 fp32+bias; rels 0..7 -> hall fp16.
__global__ __launch_bounds__(256, 1) void rgemm_fused(
    const float* __restrict__ X,
    const f16* __restrict__ Wc,
    const float* __restrict__ w1_b,
    f16* __restrict__ hall, float* __restrict__ b1, int n_rows)
{
    extern __shared__ __align__(16) char sm[];
    const uint32_t sA0 = s2u(sm);
    const uint32_t sB0 = sA0 + 2 * A_SEG;

    const int tid = threadIdx.x, lane = tid & 31, wid = tid >> 5;
    const int wm = wid & 1, wn = wid >> 1;
    const int row0 = blockIdx.x * 128;

    // ---- stage fp32 x tile into sB area (69632 >= 65536), split to sA hi/lo ----
    {
        const int r = tid >> 1, h = tid & 1;
        const int gr = row0 + r;
#pragma unroll
        for (int i = 0; i < 16; ++i)
            cp16z(sB0 + r * 512 + h * 256 + i * 16,
                  X + (size_t)gr * 128 + h * 64 + i * 4, gr < n_rows ? 16 : 0);
        cp_commit();
        cp_wait<0>();
        __syncthreads();
#pragma unroll
        for (int j = 0; j < 32; ++j) {
            int col = h * 64 + j * 2;
            float2 v = *(const float2*)(sm + 2 * A_SEG + r * 512 + col * 4);
            f16 h0 = __float2half_rn(v.x), h1 = __float2half_rn(v.y);
            uint32_t o = (col >> 5) * A_CHUNK + r * A_STRIDE + (col & 31) * 2;
            *(__half2*)(sm + o) = __halves2half2(h0, h1);
            *(__half2*)(sm + A_SEG + o) = __halves2half2(
                __float2half_rn(v.x - __half2float(h0)),
                __float2half_rn(v.y - __half2float(h1)));
        }
        __syncthreads();
    }

    const int br = tid >> 4, bq = tid & 15;
    auto matOf = [&](int i) { return (i == 0) ? 8 : (i - 1); };
    auto loadB = [&](int mat, int buf) {
        const f16* g = Wc + (size_t)mat * 16384;
#pragma unroll
        for (int c = 0; c < 4; ++c) {
            cp16z(sB0 + buf * B_SEG + c * B_CHUNK + br * B_STRIDE + bq * 16,
                  g + (size_t)(c * 32 + br) * 128 + bq * 8, 16);
            cp16z(sB0 + buf * B_SEG + c * B_CHUNK + (br + 16) * B_STRIDE + bq * 16,
                  g + (size_t)(c * 32 + br + 16) * 128 + bq * 8, 16);
        }
    };
    loadB(matOf(0), 0);
    cp_commit();

    float acc[4][4][4];
#pragma unroll
    for (int f = 0; f < 4; ++f)
#pragma unroll
        for (int g = 0; g < 4; ++g)
#pragma unroll
            for (int r = 0; r < 4; ++r) acc[f][g][r] = 0.f;

    const int arow = lane & 15, ahalf = lane >> 4;
    const int blrow = lane & 15, bnc = (lane >> 4) * 8;
    const int tr = lane >> 2, tc = (lane & 3) * 2;

    for (int i = 0; i < 9; ++i) {
        const int buf = i & 1;
        cp_wait<0>();
        __syncthreads();
        if (i < 8) { loadB(matOf(i + 1), buf ^ 1); cp_commit(); }

        const uint32_t bB = sB0 + buf * B_SEG;
#pragma unroll
        for (int c = 0; c < 4; ++c) {
#pragma unroll
            for (int s = 0; s < 2; ++s) {
                uint32_t ah[4][4], al[4][4], bb[2][4];
#pragma unroll
                for (int f = 0; f < 4; ++f) {
                    uint32_t aa = sA0 + c * A_CHUNK + (wm * 64 + f * 16 + arow) * A_STRIDE
                                + (s * 2 + ahalf) * 16;
                    ldsm4(aa,         ah[f][0], ah[f][1], ah[f][2], ah[f][3]);
                    ldsm4(aa + A_SEG, al[f][0], al[f][1], al[f][2], al[f][3]);
                }
#pragma unroll
                for (int g = 0; g < 2; ++g) {
                    uint32_t ba = bB + c * B_CHUNK + (s * 16 + blrow) * B_STRIDE
                                + (wn * 32 + g * 16 + bnc) * 2;
                    ldsm4t(ba, bb[g][0], bb[g][1], bb[g][2], bb[g][3]);
                }
#pragma unroll
                for (int f = 0; f < 4; ++f) {
#pragma unroll
                    for (int g = 0; g < 2; ++g) {
                        mma16816h(acc[f][g*2+0][0], acc[f][g*2+0][1], acc[f][g*2+0][2], acc[f][g*2+0][3],
                                  ah[f][0], ah[f][1], ah[f][2], ah[f][3], bb[g][0], bb[g][1]);
                        mma16816h(acc[f][g*2+1][0], acc[f][g*2+1][1], acc[f][g*2+1][2], acc[f][g*2+1][3],
                                  ah[f][0], ah[f][1], ah[f][2], ah[f][3], bb[g][2], bb[g][3]);
                        mma16816h(acc[f][g*2+0][0], acc[f][g*2+0][1], acc[f][g*2+0][2], acc[f][g*2+0][3],
                                  al[f][0], al[f][1], al[f][2], al[f][3], bb[g][0], bb[g][1]);
                        mma16816h(acc[f][g*2+1][0], acc[f][g*2+1][1], acc[f][g*2+1][2], acc[f][g*2+1][3],
                                  al[f][0], al[f][1], al[f][2], al[f][3], bb[g][2], bb[g][3]);
                    }
                }
            }
        }

        const int mat = matOf(i);
#pragma unroll
        for (int f = 0; f < 4; ++f) {
            int m0 = row0 + wm * 64 + f * 16 + tr;
            int m1 = m0 + 8;
#pragma unroll
            for (int g = 0; g < 4; ++g) {
                int col = wn * 32 + g * 8 + tc;
                if (mat < 8) {
                    f16* C = hall + (size_t)mat * Nn * 128;
                    if (m0 < n_rows)
                        *(__half2*)(C + (size_t)m0 * 128 + col) =
                            __floats2half2_rn(acc[f][g][0], acc[f][g][1]);
                    if (m1 < n_rows)
                        *(__half2*)(C + (size_t)m1 * 128 + col) =
                            __floats2half2_rn(acc[f][g][2], acc[f][g][3]);
                } else {
                    float bb0 = w1_b[col], bb1 = w1_b[col + 1];
                    if (m0 < n_rows) *(float2*)(b1 + (size_t)m0 * 128 + col) =
                        make_float2(acc[f][g][0] + bb0, acc[f][g][1] + bb1);
                    if (m1 < n_rows) *(float2*)(b1 + (size_t)m1 * 128 + col) =
                        make_float2(acc[f][g][2] + bb0, acc[f][g][3] + bb1);
                }
                acc[f][g][0] = acc[f][g][1] = acc[f][g][2] = acc[f][g][3] = 0.f;
            }
        }
    }
}

// ================= fused MLP, 64-row tiles, fp16 2-pass =================
__global__ __launch_bounds__(256, 2) void mlp_fused64(
    const float* __restrict__ B1,
    const f16* __restrict__ M1, const f16* __restrict__ M2,
    const float* __restrict__ m1_b, const float* __restrict__ m2_b,
    float* __restrict__ out, int n_rows)
{
    extern __shared__ __align__(16) char sm[];
    const uint32_t sA0 = s2u(sm);
    const uint32_t sB0 = sA0 + 2 * A_SEG64;

    const int tid = threadIdx.x, lane = tid & 31, wid = tid >> 5;
    const int wm = wid & 1, wn = wid >> 1;
    const int row0 = blockIdx.x * 64;

    const int br = tid >> 4, bq = tid & 15;
    auto loadB = [&](const f16* g) {
#pragma unroll
        for (int c = 0; c < 4; ++c) {
            cp16z(sB0 + c * B_CHUNK + br * B_STRIDE + bq * 16,
                  g + (size_t)(c * 32 + br) * 128 + bq * 8, 16);
            cp16z(sB0 + c * B_CHUNK + (br + 16) * B_STRIDE + bq * 16,
                  g + (size_t)(c * 32 + br + 16) * 128 + bq * 8, 16);
        }
    };
    loadB(M1);
    cp_commit();

    // ---- split b1 tile directly from global: 4 threads/row ----
    {
        const int r = tid >> 2;
        const int c0 = (tid & 3) * 32;
        const int gr = row0 + r;
        const bool ok = gr < n_rows;
#pragma unroll
        for (int j = 0; j < 16; ++j) {
            int col = c0 + j * 2;
            float2 v = ok ? *(const float2*)(B1 + (size_t)gr * 128 + col)
                          : make_float2(0.f, 0.f);
            f16 h0 = __float2half_rn(v.x), h1 = __float2half_rn(v.y);
            uint32_t o = (col >> 5) * A_CHUNK64 + r * A_STRIDE + (col & 31) * 2;
            *(__half2*)(sm + o) = __halves2half2(h0, h1);
            *(__half2*)(sm + A_SEG64 + o) = __halves2half2(
                __float2half_rn(v.x - __half2float(h0)),
                __float2half_rn(v.y - __half2float(h1)));
        }
    }
    cp_wait<0>();
    __syncthreads();

    float acc[2][4][4];
#pragma unroll
    for (int f = 0; f < 2; ++f)
#pragma unroll
        for (int g = 0; g < 4; ++g)
#pragma unroll
            for (int r = 0; r < 4; ++r) acc[f][g][r] = 0.f;

    const int arow = lane & 15, ahalf = lane >> 4;
    const int blrow = lane & 15, bnc = (lane >> 4) * 8;
    const int tr = lane >> 2, tc = (lane & 3) * 2;

    auto mma_pass = [&]() {
#pragma unroll
        for (int c = 0; c < 4; ++c) {
#pragma unroll
            for (int s = 0; s < 2; ++s) {
                uint32_t ah[2][4], al[2][4], bb[2][4];
#pragma unroll
                for (int f = 0; f < 2; ++f) {
                    uint32_t aa = sA0 + c * A_CHUNK64 + (wm * 32 + f * 16 + arow) * A_STRIDE
                                + (s * 2 + ahalf) * 16;
                    ldsm4(aa,           ah[f][0], ah[f][1], ah[f][2], ah[f][3]);
                    ldsm4(aa + A_SEG64, al[f][0], al[f][1], al[f][2], al[f][3]);
                }
#pragma unroll
                for (int g = 0; g < 2; ++g) {
                    uint32_t ba = sB0 + c * B_CHUNK + (s * 16 + blrow) * B_STRIDE
                                + (wn * 32 + g * 16 + bnc) * 2;
                    ldsm4t(ba, bb[g][0], bb[g][1], bb[g][2], bb[g][3]);
                }
#pragma unroll
                for (int f = 0; f < 2; ++f) {
#pragma unroll
                    for (int g = 0; g < 2; ++g) {
                        mma16816h(acc[f][g*2+0][0], acc[f][g*2+0][1], acc[f][g*2+0][2], acc[f][g*2+0][3],
                                  ah[f][0], ah[f][1], ah[f][2], ah[f][3], bb[g][0], bb[g][1]);
                        mma16816h(acc[f][g*2+1][0], acc[f][g*2+1][1], acc[f][g*2+1][2], acc[f][g*2+1][3],
                                  ah[f][0], ah[f][1], ah[f][2], ah[f][3], bb[g][2], bb[g][3]);
                        mma16816h(acc[f][g*2+0][0], acc[f][g*2+0][1], acc[f][g*2+0][2], acc[f][g*2+0][3],
                                  al[f][0], al[f][1], al[f][2], al[f][3], bb[g][0], bb[g][1]);
                        mma16816h(acc[f][g*2+1][0], acc[f][g*2+1][1], acc[f][g*2+1][2], acc[f][g*2+1][3],
                                  al[f][0], al[f][1], al[f][2], al[f][3], bb[g][2], bb[g][3]);
                    }
                }
            }
        }
    };

    // ---- GEMM 1: b1 @ m1 ----
    mma_pass();
    __syncthreads();

    loadB(M2);
    cp_commit();

    // bias + relu + split -> sA (b2 tile, fp16 hi/lo)
#pragma unroll
    for (int f = 0; f < 2; ++f) {
        int r0l = wm * 32 + f * 16 + tr;
        int r1l = r0l + 8;
#pragma unroll
        for (int g = 0; g < 4; ++g) {
            int col = wn * 32 + g * 8 + tc;
            float bb0 = m1_b[col], bb1 = m1_b[col + 1];
            float v00 = fmaxf(acc[f][g][0] + bb0, 0.f);
            float v01 = fmaxf(acc[f][g][1] + bb1, 0.f);
            float v10 = fmaxf(acc[f][g][2] + bb0, 0.f);
            float v11 = fmaxf(acc[f][g][3] + bb1, 0.f);
            uint32_t off0 = (col >> 5) * A_CHUNK64 + r0l * A_STRIDE + (col & 31) * 2;
            uint32_t off1 = (col >> 5) * A_CHUNK64 + r1l * A_STRIDE + (col & 31) * 2;
            f16 h00 = __float2half_rn(v00), h01 = __float2half_rn(v01);
            f16 h10 = __float2half_rn(v10), h11 = __float2half_rn(v11);
            *(__half2*)(sm + off0) = __halves2half2(h00, h01);
            *(__half2*)(sm + off1) = __halves2half2(h10, h11);
            *(__half2*)(sm + A_SEG64 + off0) = __halves2half2(
                __float2half_rn(v00 - __half2float(h00)),
                __float2half_rn(v01 - __half2float(h01)));
            *(__half2*)(sm + A_SEG64 + off1) = __halves2half2(
                __float2half_rn(v10 - __half2float(h10)),
                __float2half_rn(v11 - __half2float(h11)));
            acc[f][g][0] = acc[f][g][1] = acc[f][g][2] = acc[f][g][3] = 0.f;
        }
    }
    cp_wait<0>();
    __syncthreads();

    // ---- GEMM 2: b2 @ m2 ----
    mma_pass();

#pragma unroll
    for (int f = 0; f < 2; ++f) {
        int m0 = row0 + wm * 32 + f * 16 + tr;
        int m1 = m0 + 8;
#pragma unroll
        for (int g = 0; g < 4; ++g) {
            int col = wn * 32 + g * 8 + tc;
            float bb0 = m2_b[col], bb1 = m2_b[col + 1];
            if (m0 < n_rows)
                *(float2*)(out + (size_t)m0 * 128 + col) =
                    make_float2(acc[f][g][0] + bb0, acc[f][g][1] + bb1);
            if (m1 < n_rows)
                *(float2*)(out + (size_t)m1 * 128 + col) =
                    make_float2(acc[f][g][2] + bb0, acc[f][g][3] + bb1);
        }
    }
}

// ---------------- merged weight convert (fp32 -> single fp16) ----------------
__global__ __launch_bounds__(256) void wconv_kernel(
    const float4* __restrict__ Wrel, const float4* __restrict__ w1W,
    const float4* __restrict__ m1W,  const float4* __restrict__ m2W,
    __half2* __restrict__ Wc, __half2* __restrict__ m1, __half2* __restrict__ m2)
{
    int i = blockIdx.x * 256 + threadIdx.x;
    if (i >= 11 * 4096) return;
    const int mat = i >> 12, local = i & 4095;
    const float4* in;
    __half2* o;
    if (mat < 8)       { in = Wrel + i;    o = Wc + i * 2; }
    else if (mat == 8) { in = w1W + local; o = Wc + (8 * 4096 + local) * 2; }
    else if (mat == 9) { in = m1W + local; o = m1 + local * 2; }
    else               { in = m2W + local; o = m2 + local * 2; }
    float4 v = *in;
    o[0] = __floats2half2_rn(v.x, v.y);
    o[1] = __floats2half2_rn(v.z, v.w);
}

// ---------------- edge scatter: 4 edges/warp, fp16 hall (R13 proven) ----------
__global__ __launch_bounds__(256) void edge_scatter(
    const f16* __restrict__ hall,
    const int* __restrict__ src, const int* __restrict__ dst,
    const int* __restrict__ etype, float* __restrict__ agg)
{
    const int w    = (blockIdx.x * 256 + threadIdx.x) >> 5;
    const int lane = threadIdx.x & 31;
    const int e0   = w * 4;
    if (e0 >= Ee) return;

    int s[4], d[4], t[4];
#pragma unroll
    for (int i = 0; i < 4; ++i) {
        s[i] = __ldg(src + e0 + i);
        d[i] = __ldg(dst + e0 + i);
        t[i] = __ldg(etype + e0 + i);
    }
    __half2 v[4][2];
#pragma unroll
    for (int i = 0; i < 4; ++i) {
        const __half2* row = (const __half2*)(hall + ((size_t)t[i] * Nn + s[i]) * 128);
        uint2 raw = *(const uint2*)(row + lane * 2);
        v[i][0] = *(__half2*)&raw.x;
        v[i][1] = *(__half2*)&raw.y;
    }
#pragma unroll
    for (int i = 0; i < 4; ++i) {
        float2 a = __half22float2(v[i][0]);
        float2 b = __half22float2(v[i][1]);
        float* o = agg + (size_t)d[i] * 128 + lane * 4;
        asm volatile("red.global.add.v4.f32 [%0], {%1,%2,%3,%4};"
                     :: "l"(o), "f"(a.x), "f"(a.y), "f"(b.x), "f"(b.y) : "memory");
    }
}

// ---------------- launch ----------------
extern "C" void kernel_launch(void* const* d_in, const int* in_sizes, int n_in,
                              void* d_out, int out_size)
{
    const float* x     = (const float*)d_in[0];
    const int*   src   = (const int*)  d_in[1];
    const int*   dst   = (const int*)  d_in[2];
    const int*   etype = (const int*)  d_in[3];
    const float* W_rel = (const float*)d_in[4];
    const float* w1_W  = (const float*)d_in[5];
    const float* w1_b  = (const float*)d_in[6];
    const float* m1_W  = (const float*)d_in[7];
    const float* m1_b  = (const float*)d_in[8];
    const float* m2_W  = (const float*)d_in[9];
    const float* m2_b  = (const float*)d_in[10];
    float* out = (float*)d_out;

    f16 *hall, *Wc, *m1, *m2;
    float* b1;
    cudaGetSymbolAddress((void**)&hall, g_hall);
    cudaGetSymbolAddress((void**)&b1,   g_b1);
    cudaGetSymbolAddress((void**)&Wc,   g_Wc);
    cudaGetSymbolAddress((void**)&m1,   g_m1);
    cudaGetSymbolAddress((void**)&m2,   g_m2);

    cudaFuncSetAttribute(rgemm_fused, cudaFuncAttributeMaxDynamicSharedMemorySize, FUSED_SMEM);
    cudaFuncSetAttribute(mlp_fused64, cudaFuncAttributeMaxDynamicSharedMemorySize, MLP64_SMEM);

    const int nTiles   = (Nn + 127) / 128;  // 391
    const int nTiles64 = (Nn + 63) / 64;    // 782
    const int sgrid    = (Ee + 31) / 32;    // 4 edges/warp -> 20000 blocks

    wconv_kernel<<<(11 * 4096 + 255) / 256, 256>>>(
        (const float4*)W_rel, (const float4*)w1_W,
        (const float4*)m1_W, (const float4*)m2_W,
        (__half2*)Wc, (__half2*)m1, (__half2*)m2);

    // hall[r] = x @ W_rel[r] (fp16); b1 = x @ w1 + w1_b (fp32)
    rgemm_fused<<<nTiles, 256, FUSED_SMEM>>>(x, Wc, w1_b, hall, b1, Nn);

    // b1[dst] += hall[etype, src]
    edge_scatter<<<sgrid, 256>>>(hall, src, dst, etype, b1);

    // out = relu(b1 @ m1 + b) @ m2 + b
    mlp_fused64<<<nTiles64, 256, MLP64_SMEM>>>(b1, m1, m2, m1_b, m2_b, out, Nn);
}

// round 17
// speedup vs baseline: 1.3735x; 1.1213x over previous
#include <cuda_runtime.h>
#include <cuda_fp16.h>
#include <cstdint>

#define Nn 50000
#define Ee 640000
#define Rr 8
typedef __half f16;

// ---------------- scratch ----------------
__device__ f16   g_hall[(size_t)Rr * Nn * 128];   // fp16 messages
__device__ float g_b1[(size_t)Nn * 128];
__device__ f16   g_Wc[9 * 128 * 128];             // 8 rels + w1, single fp16
__device__ f16   g_m1[128 * 128], g_m2[128 * 128];

// ---------------- asm helpers ----------------
__device__ __forceinline__ uint32_t s2u(const void* p) {
    return (uint32_t)__cvta_generic_to_shared(p);
}
__device__ __forceinline__ void cp16z(uint32_t d, const void* s, int sz) {
    asm volatile("cp.async.cg.shared.global [%0],[%1],16,%2;\n" :: "r"(d), "l"(s), "r"(sz));
}
__device__ __forceinline__ void cp_commit() { asm volatile("cp.async.commit_group;\n"); }
template<int N> __device__ __forceinline__ void cp_wait() {
    asm volatile("cp.async.wait_group %0;\n" :: "n"(N));
}
__device__ __forceinline__ void ldsm4(uint32_t a, uint32_t& r0, uint32_t& r1,
                                      uint32_t& r2, uint32_t& r3) {
    asm volatile("ldmatrix.sync.aligned.m8n8.x4.shared.b16 {%0,%1,%2,%3}, [%4];"
                 : "=r"(r0), "=r"(r1), "=r"(r2), "=r"(r3) : "r"(a));
}
__device__ __forceinline__ void ldsm4t(uint32_t a, uint32_t& r0, uint32_t& r1,
                                       uint32_t& r2, uint32_t& r3) {
    asm volatile("ldmatrix.sync.aligned.m8n8.x4.trans.shared.b16 {%0,%1,%2,%3}, [%4];"
                 : "=r"(r0), "=r"(r1), "=r"(r2), "=r"(r3) : "r"(a));
}
__device__ __forceinline__ void mma16816h(float& d0, float& d1, float& d2, float& d3,
                                          uint32_t a0, uint32_t a1, uint32_t a2, uint32_t a3,
                                          uint32_t b0, uint32_t b1) {
    asm volatile(
        "mma.sync.aligned.m16n8k16.row.col.f32.f16.f16.f32 "
        "{%0,%1,%2,%3}, {%4,%5,%6,%7}, {%8,%9}, {%0,%1,%2,%3};"
        : "+f"(d0), "+f"(d1), "+f"(d2), "+f"(d3)
        : "r"(a0), "r"(a1), "r"(a2), "r"(a3), "r"(b0), "r"(b1));
}

#define A_STRIDE 80
#define A_CHUNK  (128 * A_STRIDE)   // 10240
#define A_SEG    (4 * A_CHUNK)      // 40960
#define B_STRIDE 272
#define B_CHUNK  (32 * B_STRIDE)    // 8704
#define B_SEG    (4 * B_CHUNK)      // 34816
#define FUSED_SMEM (2 * A_SEG + 2 * B_SEG)   // 151552

// mlp64: 64-row tiles
#define A_CHUNK64 (64 * A_STRIDE)   // 5120
#define A_SEG64   (4 * A_CHUNK64)   // 20480
#define MLP64_SMEM (2 * A_SEG64 + B_SEG)     // 75776 -> 2 CTAs/SM

// ================= fused relation GEMM =================
// i=0: w1, 2-pass (Ahi+Alo) -> b1 fp32+bias.  i=1..8: rels, hi-only -> hall fp16.
__global__ __launch_bounds__(256, 1) void rgemm_fused(
    const float* __restrict__ X,
    const f16* __restrict__ Wc,
    const float* __restrict__ w1_b,
    f16* __restrict__ hall, float* __restrict__ b1, int n_rows)
{
    extern __shared__ __align__(16) char sm[];
    const uint32_t sA0 = s2u(sm);
    const uint32_t sB0 = sA0 + 2 * A_SEG;

    const int tid = threadIdx.x, lane = tid & 31, wid = tid >> 5;
    const int wm = wid & 1, wn = wid >> 1;
    const int row0 = blockIdx.x * 128;

    // ---- stage fp32 x tile into sB area, split to sA hi/lo ----
    {
        const int r = tid >> 1, h = tid & 1;
        const int gr = row0 + r;
#pragma unroll
        for (int i = 0; i < 16; ++i)
            cp16z(sB0 + r * 512 + h * 256 + i * 16,
                  X + (size_t)gr * 128 + h * 64 + i * 4, gr < n_rows ? 16 : 0);
        cp_commit();
        cp_wait<0>();
        __syncthreads();
#pragma unroll
        for (int j = 0; j < 32; ++j) {
            int col = h * 64 + j * 2;
            float2 v = *(const float2*)(sm + 2 * A_SEG + r * 512 + col * 4);
            f16 h0 = __float2half_rn(v.x), h1 = __float2half_rn(v.y);
            uint32_t o = (col >> 5) * A_CHUNK + r * A_STRIDE + (col & 31) * 2;
            *(__half2*)(sm + o) = __halves2half2(h0, h1);
            *(__half2*)(sm + A_SEG + o) = __halves2half2(
                __float2half_rn(v.x - __half2float(h0)),
                __float2half_rn(v.y - __half2float(h1)));
        }
        __syncthreads();
    }

    const int br = tid >> 4, bq = tid & 15;
    auto matOf = [&](int i) { return (i == 0) ? 8 : (i - 1); };
    auto loadB = [&](int mat, int buf) {
        const f16* g = Wc + (size_t)mat * 16384;
#pragma unroll
        for (int c = 0; c < 4; ++c) {
            cp16z(sB0 + buf * B_SEG + c * B_CHUNK + br * B_STRIDE + bq * 16,
                  g + (size_t)(c * 32 + br) * 128 + bq * 8, 16);
            cp16z(sB0 + buf * B_SEG + c * B_CHUNK + (br + 16) * B_STRIDE + bq * 16,
                  g + (size_t)(c * 32 + br + 16) * 128 + bq * 8, 16);
        }
    };
    loadB(matOf(0), 0);
    cp_commit();

    float acc[4][4][4];
#pragma unroll
    for (int f = 0; f < 4; ++f)
#pragma unroll
        for (int g = 0; g < 4; ++g)
#pragma unroll
            for (int r = 0; r < 4; ++r) acc[f][g][r] = 0.f;

    const int arow = lane & 15, ahalf = lane >> 4;
    const int blrow = lane & 15, bnc = (lane >> 4) * 8;
    const int tr = lane >> 2, tc = (lane & 3) * 2;

    // hi-only pass (relations)
    auto pass_hi = [&](uint32_t bB) {
#pragma unroll
        for (int c = 0; c < 4; ++c) {
#pragma unroll
            for (int s = 0; s < 2; ++s) {
                uint32_t ah[4][4], bb[2][4];
#pragma unroll
                for (int f = 0; f < 4; ++f) {
                    uint32_t aa = sA0 + c * A_CHUNK + (wm * 64 + f * 16 + arow) * A_STRIDE
                                + (s * 2 + ahalf) * 16;
                    ldsm4(aa, ah[f][0], ah[f][1], ah[f][2], ah[f][3]);
                }
#pragma unroll
                for (int g = 0; g < 2; ++g) {
                    uint32_t ba = bB + c * B_CHUNK + (s * 16 + blrow) * B_STRIDE
                                + (wn * 32 + g * 16 + bnc) * 2;
                    ldsm4t(ba, bb[g][0], bb[g][1], bb[g][2], bb[g][3]);
                }
#pragma unroll
                for (int f = 0; f < 4; ++f) {
#pragma unroll
                    for (int g = 0; g < 2; ++g) {
                        mma16816h(acc[f][g*2+0][0], acc[f][g*2+0][1], acc[f][g*2+0][2], acc[f][g*2+0][3],
                                  ah[f][0], ah[f][1], ah[f][2], ah[f][3], bb[g][0], bb[g][1]);
                        mma16816h(acc[f][g*2+1][0], acc[f][g*2+1][1], acc[f][g*2+1][2], acc[f][g*2+1][3],
                                  ah[f][0], ah[f][1], ah[f][2], ah[f][3], bb[g][2], bb[g][3]);
                    }
                }
            }
        }
    };
    // hi+lo pass (w1 only)
    auto pass_hilo = [&](uint32_t bB) {
#pragma unroll
        for (int c = 0; c < 4; ++c) {
#pragma unroll
            for (int s = 0; s < 2; ++s) {
                uint32_t ah[4][4], al[4][4], bb[2][4];
#pragma unroll
                for (int f = 0; f < 4; ++f) {
                    uint32_t aa = sA0 + c * A_CHUNK + (wm * 64 + f * 16 + arow) * A_STRIDE
                                + (s * 2 + ahalf) * 16;
                    ldsm4(aa,         ah[f][0], ah[f][1], ah[f][2], ah[f][3]);
                    ldsm4(aa + A_SEG, al[f][0], al[f][1], al[f][2], al[f][3]);
                }
#pragma unroll
                for (int g = 0; g < 2; ++g) {
                    uint32_t ba = bB + c * B_CHUNK + (s * 16 + blrow) * B_STRIDE
                                + (wn * 32 + g * 16 + bnc) * 2;
                    ldsm4t(ba, bb[g][0], bb[g][1], bb[g][2], bb[g][3]);
                }
#pragma unroll
                for (int f = 0; f < 4; ++f) {
#pragma unroll
                    for (int g = 0; g < 2; ++g) {
                        mma16816h(acc[f][g*2+0][0], acc[f][g*2+0][1], acc[f][g*2+0][2], acc[f][g*2+0][3],
                                  ah[f][0], ah[f][1], ah[f][2], ah[f][3], bb[g][0], bb[g][1]);
                        mma16816h(acc[f][g*2+1][0], acc[f][g*2+1][1], acc[f][g*2+1][2], acc[f][g*2+1][3],
                                  ah[f][0], ah[f][1], ah[f][2], ah[f][3], bb[g][2], bb[g][3]);
                        mma16816h(acc[f][g*2+0][0], acc[f][g*2+0][1], acc[f][g*2+0][2], acc[f][g*2+0][3],
                                  al[f][0], al[f][1], al[f][2], al[f][3], bb[g][0], bb[g][1]);
                        mma16816h(acc[f][g*2+1][0], acc[f][g*2+1][1], acc[f][g*2+1][2], acc[f][g*2+1][3],
                                  al[f][0], al[f][1], al[f][2], al[f][3], bb[g][2], bb[g][3]);
                    }
                }
            }
        }
    };

    for (int i = 0; i < 9; ++i) {
        const int buf = i & 1;
        cp_wait<0>();
        __syncthreads();
        if (i < 8) { loadB(matOf(i + 1), buf ^ 1); cp_commit(); }

        const uint32_t bB = sB0 + buf * B_SEG;
        if (i == 0) pass_hilo(bB);
        else        pass_hi(bB);

        const int mat = matOf(i);
#pragma unroll
        for (int f = 0; f < 4; ++f) {
            int m0 = row0 + wm * 64 + f * 16 + tr;
            int m1 = m0 + 8;
#pragma unroll
            for (int g = 0; g < 4; ++g) {
                int col = wn * 32 + g * 8 + tc;
                if (mat < 8) {
                    f16* C = hall + (size_t)mat * Nn * 128;
                    if (m0 < n_rows)
                        *(__half2*)(C + (size_t)m0 * 128 + col) =
                            __floats2half2_rn(acc[f][g][0], acc[f][g][1]);
                    if (m1 < n_rows)
                        *(__half2*)(C + (size_t)m1 * 128 + col) =
                            __floats2half2_rn(acc[f][g][2], acc[f][g][3]);
                } else {
                    float bb0 = w1_b[col], bb1 = w1_b[col + 1];
                    if (m0 < n_rows) *(float2*)(b1 + (size_t)m0 * 128 + col) =
                        make_float2(acc[f][g][0] + bb0, acc[f][g][1] + bb1);
                    if (m1 < n_rows) *(float2*)(b1 + (size_t)m1 * 128 + col) =
                        make_float2(acc[f][g][2] + bb0, acc[f][g][3] + bb1);
                }
                acc[f][g][0] = acc[f][g][1] = acc[f][g][2] = acc[f][g][3] = 0.f;
            }
        }
    }
}

// ================= fused MLP, 64-row tiles, fp16 2-pass (R16 proven) =============
__global__ __launch_bounds__(256, 2) void mlp_fused64(
    const float* __restrict__ B1,
    const f16* __restrict__ M1, const f16* __restrict__ M2,
    const float* __restrict__ m1_b, const float* __restrict__ m2_b,
    float* __restrict__ out, int n_rows)
{
    extern __shared__ __align__(16) char sm[];
    const uint32_t sA0 = s2u(sm);
    const uint32_t sB0 = sA0 + 2 * A_SEG64;

    const int tid = threadIdx.x, lane = tid & 31, wid = tid >> 5;
    const int wm = wid & 1, wn = wid >> 1;
    const int row0 = blockIdx.x * 64;

    const int br = tid >> 4, bq = tid & 15;
    auto loadB = [&](const f16* g) {
#pragma unroll
        for (int c = 0; c < 4; ++c) {
            cp16z(sB0 + c * B_CHUNK + br * B_STRIDE + bq * 16,
                  g + (size_t)(c * 32 + br) * 128 + bq * 8, 16);
            cp16z(sB0 + c * B_CHUNK + (br + 16) * B_STRIDE + bq * 16,
                  g + (size_t)(c * 32 + br + 16) * 128 + bq * 8, 16);
        }
    };
    loadB(M1);
    cp_commit();

    {
        const int r = tid >> 2;
        const int c0 = (tid & 3) * 32;
        const int gr = row0 + r;
        const bool ok = gr < n_rows;
#pragma unroll
        for (int j = 0; j < 16; ++j) {
            int col = c0 + j * 2;
            float2 v = ok ? *(const float2*)(B1 + (size_t)gr * 128 + col)
                          : make_float2(0.f, 0.f);
            f16 h0 = __float2half_rn(v.x), h1 = __float2half_rn(v.y);
            uint32_t o = (col >> 5) * A_CHUNK64 + r * A_STRIDE + (col & 31) * 2;
            *(__half2*)(sm + o) = __halves2half2(h0, h1);
            *(__half2*)(sm + A_SEG64 + o) = __halves2half2(
                __float2half_rn(v.x - __half2float(h0)),
                __float2half_rn(v.y - __half2float(h1)));
        }
    }
    cp_wait<0>();
    __syncthreads();

    float acc[2][4][4];
#pragma unroll
    for (int f = 0; f < 2; ++f)
#pragma unroll
        for (int g = 0; g < 4; ++g)
#pragma unroll
            for (int r = 0; r < 4; ++r) acc[f][g][r] = 0.f;

    const int arow = lane & 15, ahalf = lane >> 4;
    const int blrow = lane & 15, bnc = (lane >> 4) * 8;
    const int tr = lane >> 2, tc = (lane & 3) * 2;

    auto mma_pass = [&]() {
#pragma unroll
        for (int c = 0; c < 4; ++c) {
#pragma unroll
            for (int s = 0; s < 2; ++s) {
                uint32_t ah[2][4], al[2][4], bb[2][4];
#pragma unroll
                for (int f = 0; f < 2; ++f) {
                    uint32_t aa = sA0 + c * A_CHUNK64 + (wm * 32 + f * 16 + arow) * A_STRIDE
                                + (s * 2 + ahalf) * 16;
                    ldsm4(aa,           ah[f][0], ah[f][1], ah[f][2], ah[f][3]);
                    ldsm4(aa + A_SEG64, al[f][0], al[f][1], al[f][2], al[f][3]);
                }
#pragma unroll
                for (int g = 0; g < 2; ++g) {
                    uint32_t ba = sB0 + c * B_CHUNK + (s * 16 + blrow) * B_STRIDE
                                + (wn * 32 + g * 16 + bnc) * 2;
                    ldsm4t(ba, bb[g][0], bb[g][1], bb[g][2], bb[g][3]);
                }
#pragma unroll
                for (int f = 0; f < 2; ++f) {
#pragma unroll
                    for (int g = 0; g < 2; ++g) {
                        mma16816h(acc[f][g*2+0][0], acc[f][g*2+0][1], acc[f][g*2+0][2], acc[f][g*2+0][3],
                                  ah[f][0], ah[f][1], ah[f][2], ah[f][3], bb[g][0], bb[g][1]);
                        mma16816h(acc[f][g*2+1][0], acc[f][g*2+1][1], acc[f][g*2+1][2], acc[f][g*2+1][3],
                                  ah[f][0], ah[f][1], ah[f][2], ah[f][3], bb[g][2], bb[g][3]);
                        mma16816h(acc[f][g*2+0][0], acc[f][g*2+0][1], acc[f][g*2+0][2], acc[f][g*2+0][3],
                                  al[f][0], al[f][1], al[f][2], al[f][3], bb[g][0], bb[g][1]);
                        mma16816h(acc[f][g*2+1][0], acc[f][g*2+1][1], acc[f][g*2+1][2], acc[f][g*2+1][3],
                                  al[f][0], al[f][1], al[f][2], al[f][3], bb[g][2], bb[g][3]);
                    }
                }
            }
        }
    };

    mma_pass();
    __syncthreads();

    loadB(M2);
    cp_commit();

#pragma unroll
    for (int f = 0; f < 2; ++f) {
        int r0l = wm * 32 + f * 16 + tr;
        int r1l = r0l + 8;
#pragma unroll
        for (int g = 0; g < 4; ++g) {
            int col = wn * 32 + g * 8 + tc;
            float bb0 = m1_b[col], bb1 = m1_b[col + 1];
            float v00 = fmaxf(acc[f][g][0] + bb0, 0.f);
            float v01 = fmaxf(acc[f][g][1] + bb1, 0.f);
            float v10 = fmaxf(acc[f][g][2] + bb0, 0.f);
            float v11 = fmaxf(acc[f][g][3] + bb1, 0.f);
            uint32_t off0 = (col >> 5) * A_CHUNK64 + r0l * A_STRIDE + (col & 31) * 2;
            uint32_t off1 = (col >> 5) * A_CHUNK64 + r1l * A_STRIDE + (col & 31) * 2;
            f16 h00 = __float2half_rn(v00), h01 = __float2half_rn(v01);
            f16 h10 = __float2half_rn(v10), h11 = __float2half_rn(v11);
            *(__half2*)(sm + off0) = __halves2half2(h00, h01);
            *(__half2*)(sm + off1) = __halves2half2(h10, h11);
            *(__half2*)(sm + A_SEG64 + off0) = __halves2half2(
                __float2half_rn(v00 - __half2float(h00)),
                __float2half_rn(v01 - __half2float(h01)));
            *(__half2*)(sm + A_SEG64 + off1) = __halves2half2(
                __float2half_rn(v10 - __half2float(h10)),
                __float2half_rn(v11 - __half2float(h11)));
            acc[f][g][0] = acc[f][g][1] = acc[f][g][2] = acc[f][g][3] = 0.f;
        }
    }
    cp_wait<0>();
    __syncthreads();

    mma_pass();

#pragma unroll
    for (int f = 0; f < 2; ++f) {
        int m0 = row0 + wm * 32 + f * 16 + tr;
        int m1 = m0 + 8;
#pragma unroll
        for (int g = 0; g < 4; ++g) {
            int col = wn * 32 + g * 8 + tc;
            float bb0 = m2_b[col], bb1 = m2_b[col + 1];
            if (m0 < n_rows)
                *(float2*)(out + (size_t)m0 * 128 + col) =
                    make_float2(acc[f][g][0] + bb0, acc[f][g][1] + bb1);
            if (m1 < n_rows)
                *(float2*)(out + (size_t)m1 * 128 + col) =
                    make_float2(acc[f][g][2] + bb0, acc[f][g][3] + bb1);
        }
    }
}

// ---------------- merged weight convert (fp32 -> single fp16) ----------------
__global__ __launch_bounds__(256) void wconv_kernel(
    const float4* __restrict__ Wrel, const float4* __restrict__ w1W,
    const float4* __restrict__ m1W,  const float4* __restrict__ m2W,
    __half2* __restrict__ Wc, __half2* __restrict__ m1, __half2* __restrict__ m2)
{
    int i = blockIdx.x * 256 + threadIdx.x;
    if (i >= 11 * 4096) return;
    const int mat = i >> 12, local = i & 4095;
    const float4* in;
    __half2* o;
    if (mat < 8)       { in = Wrel + i;    o = Wc + i * 2; }
    else if (mat == 8) { in = w1W + local; o = Wc + (8 * 4096 + local) * 2; }
    else if (mat == 9) { in = m1W + local; o = m1 + local * 2; }
    else               { in = m2W + local; o = m2 + local * 2; }
    float4 v = *in;
    o[0] = __floats2half2_rn(v.x, v.y);
    o[1] = __floats2half2_rn(v.z, v.w);
}

// ---------------- edge scatter: 4 edges/warp, fp16 hall (proven) ----------
__global__ __launch_bounds__(256) void edge_scatter(
    const f16* __restrict__ hall,
    const int* __restrict__ src, const int* __restrict__ dst,
    const int* __restrict__ etype, float* __restrict__ agg)
{
    const int w    = (blockIdx.x * 256 + threadIdx.x) >> 5;
    const int lane = threadIdx.x & 31;
    const int e0   = w * 4;
    if (e0 >= Ee) return;

    int s[4], d[4], t[4];
#pragma unroll
    for (int i = 0; i < 4; ++i) {
        s[i] = __ldg(src + e0 + i);
        d[i] = __ldg(dst + e0 + i);
        t[i] = __ldg(etype + e0 + i);
    }
    __half2 v[4][2];
#pragma unroll
    for (int i = 0; i < 4; ++i) {
        const __half2* row = (const __half2*)(hall + ((size_t)t[i] * Nn + s[i]) * 128);
        uint2 raw = *(const uint2*)(row + lane * 2);
        v[i][0] = *(__half2*)&raw.x;
        v[i][1] = *(__half2*)&raw.y;
    }
#pragma unroll
    for (int i = 0; i < 4; ++i) {
        float2 a = __half22float2(v[i][0]);
        float2 b = __half22float2(v[i][1]);
        float* o = agg + (size_t)d[i] * 128 + lane * 4;
        asm volatile("red.global.add.v4.f32 [%0], {%1,%2,%3,%4};"
                     :: "l"(o), "f"(a.x), "f"(a.y), "f"(b.x), "f"(b.y) : "memory");
    }
}

// ---------------- launch ----------------
extern "C" void kernel_launch(void* const* d_in, const int* in_sizes, int n_in,
                              void* d_out, int out_size)
{
    const float* x     = (const float*)d_in[0];
    const int*   src   = (const int*)  d_in[1];
    const int*   dst   = (const int*)  d_in[2];
    const int*   etype = (const int*)  d_in[3];
    const float* W_rel = (const float*)d_in[4];
    const float* w1_W  = (const float*)d_in[5];
    const float* w1_b  = (const float*)d_in[6];
    const float* m1_W  = (const float*)d_in[7];
    const float* m1_b  = (const float*)d_in[8];
    const float* m2_W  = (const float*)d_in[9];
    const float* m2_b  = (const float*)d_in[10];
    float* out = (float*)d_out;

    f16 *hall, *Wc, *m1, *m2;
    float* b1;
    cudaGetSymbolAddress((void**)&hall, g_hall);
    cudaGetSymbolAddress((void**)&b1,   g_b1);
    cudaGetSymbolAddress((void**)&Wc,   g_Wc);
    cudaGetSymbolAddress((void**)&m1,   g_m1);
    cudaGetSymbolAddress((void**)&m2,   g_m2);

    cudaFuncSetAttribute(rgemm_fused, cudaFuncAttributeMaxDynamicSharedMemorySize, FUSED_SMEM);
    cudaFuncSetAttribute(mlp_fused64, cudaFuncAttributeMaxDynamicSharedMemorySize, MLP64_SMEM);

    const int nTiles   = (Nn + 127) / 128;  // 391
    const int nTiles64 = (Nn + 63) / 64;    // 782
    const int sgrid    = (Ee + 31) / 32;    // 20000 blocks

    wconv_kernel<<<(11 * 4096 + 255) / 256, 256>>>(
        (const float4*)W_rel, (const float4*)w1_W,
        (const float4*)m1_W, (const float4*)m2_W,
        (__half2*)Wc, (__half2*)m1, (__half2*)m2);

    // hall[r] = xhi @ W_rel[r] (fp16, hi-only); b1 = x @ w1 + w1_b (2-pass, fp32)
    rgemm_fused<<<nTiles, 256, FUSED_SMEM>>>(x, Wc, w1_b, hall, b1, Nn);

    // b1[dst] += hall[etype, src]
    edge_scatter<<<sgrid, 256>>>(hall, src, dst, etype, b1);

    // out = relu(b1 @ m1 + b) @ m2 + b  (2-pass both)
    mlp_fused64<<<nTiles64, 256, MLP64_SMEM>>>(b1, m1, m2, m1_b, m2_b, out, Nn);
}